// round 1
// baseline (speedup 1.0000x reference)
#include <cuda_runtime.h>

#define NCLS 32
#define SOSC 30
#define EOSC 31
#define NEGV -10000.0f
#define LOG2E 1.4426950408889634f
#define LN2F  0.6931471805599453f

typedef unsigned long long u64;

__device__ __forceinline__ float ex2f(float x){ float r; asm("ex2.approx.f32 %0, %1;" : "=f"(r) : "f"(x)); return r; }
__device__ __forceinline__ float lg2f_(float x){ float r; asm("lg2.approx.f32 %0, %1;" : "=f"(r) : "f"(x)); return r; }
__device__ __forceinline__ u64 pk2(float lo, float hi){ u64 r; asm("mov.b64 %0, {%1,%2};" : "=l"(r) : "f"(lo), "f"(hi)); return r; }
__device__ __forceinline__ void up2(u64 v, float& lo, float& hi){ asm("mov.b64 {%0,%1}, %2;" : "=f"(lo), "=f"(hi) : "l"(v)); }
__device__ __forceinline__ u64 ffma2(u64 a, u64 b, u64 c){ u64 d; asm("fma.rn.f32x2 %0, %1, %2, %3;" : "=l"(d) : "l"(a), "l"(b), "l"(c)); return d; }
__device__ __forceinline__ u64 fadd2(u64 a, u64 b){ u64 d; asm("add.rn.f32x2 %0, %1, %2;" : "=l"(d) : "l"(a), "l"(b)); return d; }

// Layout: 1 warp = 2 batch elements; lane = class c.
// Each lane holds alpha_hat as f32x2 (batch0, batch1), E row duplicated as f32x2.
// Per step: p = exp(alpha_hat) -> smem (double-buffered) -> broadcast LDS.128 ->
// 32x fma.rn.f32x2 matvec -> log -> rescale by lane0 value -> mask blend.
__global__ __launch_bounds__(128)
void crf_fwd(const float* __restrict__ feats,
             const float* __restrict__ mask,
             const float* __restrict__ trans,
             float* __restrict__ out,
             int seq, int batch)
{
    __shared__ __align__(16) u64 pbuf[4][2][NCLS];
    const int lane = threadIdx.x & 31;
    const int wl   = threadIdx.x >> 5;
    const int pair = blockIdx.x * 4 + wl;
    const int npairs = (batch + 1) >> 1;
    if (pair >= npairs) return;
    const int b0 = pair * 2;
    int b1 = b0 + 1;
    const bool has_b1 = (b1 < batch);
    if (!has_b1) b1 = b0;

    // E[c,k] = exp(T[c,k]), duplicated into both f32x2 halves. NEG rows -> exact 0.
    u64 E2[NCLS];
#pragma unroll
    for (int k = 0; k < NCLS; ++k){
        float e = ex2f(trans[lane * NCLS + k] * LOG2E);
        E2[k] = pk2(e, e);
    }
    const float teos = trans[EOSC * NCLS + lane];

    float a0 = (lane == SOSC) ? 0.0f : NEGV;   // alpha_hat, batch b0
    float a1 = a0;                              // alpha_hat, batch b1
    float C0 = 0.0f, C1 = 0.0f;                 // running log-domain offsets

    const size_t fstride = (size_t)batch * NCLS;
    const float* fpA = feats + (size_t)b0 * NCLS + lane;
    const float* fpB = feats + (size_t)b1 * NCLS + lane;
    const float* mpA = mask + b0;
    const float* mpB = mask + b1;

    // 8-deep register prefetch of feats/mask (covers DRAM latency @ ~120 cyc/step)
    float fA[8], fB[8], mA[8], mB[8];
#pragma unroll
    for (int j = 0; j < 8; ++j){
        int tc = (j < seq) ? j : (seq - 1);
        fA[j] = fpA[(size_t)tc * fstride];
        fB[j] = fpB[(size_t)tc * fstride];
        mA[j] = mpA[(size_t)tc * batch];
        mB[j] = mpB[(size_t)tc * batch];
    }

    int t = 0;
    for (int t0 = 0; t0 + 8 <= seq; t0 += 8){
#pragma unroll
        for (int j = 0; j < 8; ++j){
            // p = exp(alpha_hat)  (underflow -> 0 is exactly what we want)
            float p0 = ex2f(a0 * LOG2E);
            float p1 = ex2f(a1 * LOG2E);
            const int buf = j & 1;
            pbuf[wl][buf][lane] = pk2(p0, p1);
            __syncwarp();
            const u64* pb = pbuf[wl][buf];
            u64 acc0 = 0ull, acc1 = 0ull, acc2 = 0ull, acc3 = 0ull;
#pragma unroll
            for (int k = 0; k < NCLS; k += 4){
                ulonglong2 q0 = *reinterpret_cast<const ulonglong2*>(&pb[k]);
                ulonglong2 q1 = *reinterpret_cast<const ulonglong2*>(&pb[k+2]);
                acc0 = ffma2(E2[k],   q0.x, acc0);
                acc1 = ffma2(E2[k+1], q0.y, acc1);
                acc2 = ffma2(E2[k+2], q1.x, acc2);
                acc3 = ffma2(E2[k+3], q1.y, acc3);
            }
            u64 s2 = fadd2(fadd2(acc0, acc1), fadd2(acc2, acc3));
            float s0, s1; up2(s2, s0, s1);
            s0 = fmaxf(s0, 1e-35f);   // NEG rows: s==0 -> clamp avoids -inf/NaN
            s1 = fmaxf(s1, 1e-35f);
            float r0 = fmaf(lg2f_(s0), LN2F, fA[j]);  // raw new alpha (offset C)
            float r1 = fmaf(lg2f_(s1), LN2F, fB[j]);
            float d0 = __shfl_sync(0xffffffffu, r0, 0);  // per-step rescale
            float d1 = __shfl_sync(0xffffffffu, r1, 0);
            float mk0 = mA[j], mk1 = mB[j];
            // blend: alpha_true = C + m*d + [ a + m*((r-d) - a) ]  == reference blend
            a0 = fmaf((r0 - d0) - a0, mk0, a0);
            a1 = fmaf((r1 - d1) - a1, mk1, a1);
            C0 = fmaf(mk0, d0, C0);
            C1 = fmaf(mk1, d1, C1);
            // prefetch step t0+8+j
            int tn = t0 + 8 + j;
            int tc = (tn < seq) ? tn : (seq - 1);
            fA[j] = fpA[(size_t)tc * fstride];
            fB[j] = fpB[(size_t)tc * fstride];
            mA[j] = mpA[(size_t)tc * batch];
            mB[j] = mpB[(size_t)tc * batch];
        }
        t = t0 + 8;
    }
    // tail for seq % 8 != 0 (not hit for seq=512)
    for (; t < seq; ++t){
        float p0 = ex2f(a0 * LOG2E);
        float p1 = ex2f(a1 * LOG2E);
        const int buf = t & 1;
        pbuf[wl][buf][lane] = pk2(p0, p1);
        __syncwarp();
        const u64* pb = pbuf[wl][buf];
        u64 acc0 = 0ull, acc1 = 0ull, acc2 = 0ull, acc3 = 0ull;
#pragma unroll
        for (int k = 0; k < NCLS; k += 4){
            ulonglong2 q0 = *reinterpret_cast<const ulonglong2*>(&pb[k]);
            ulonglong2 q1 = *reinterpret_cast<const ulonglong2*>(&pb[k+2]);
            acc0 = ffma2(E2[k],   q0.x, acc0);
            acc1 = ffma2(E2[k+1], q0.y, acc1);
            acc2 = ffma2(E2[k+2], q1.x, acc2);
            acc3 = ffma2(E2[k+3], q1.y, acc3);
        }
        u64 s2 = fadd2(fadd2(acc0, acc1), fadd2(acc2, acc3));
        float s0, s1; up2(s2, s0, s1);
        s0 = fmaxf(s0, 1e-35f); s1 = fmaxf(s1, 1e-35f);
        float f0 = fpA[(size_t)t * fstride];
        float f1 = fpB[(size_t)t * fstride];
        float r0 = fmaf(lg2f_(s0), LN2F, f0);
        float r1 = fmaf(lg2f_(s1), LN2F, f1);
        float d0 = __shfl_sync(0xffffffffu, r0, 0);
        float d1 = __shfl_sync(0xffffffffu, r1, 0);
        float mk0 = mpA[(size_t)t * batch];
        float mk1 = mpB[(size_t)t * batch];
        a0 = fmaf((r0 - d0) - a0, mk0, a0);
        a1 = fmaf((r1 - d1) - a1, mk1, a1);
        C0 = fmaf(mk0, d0, C0);
        C1 = fmaf(mk1, d1, C1);
    }

    // Epilogue: out[b] = C + LSE_c(alpha_hat[c] + T[EOS,c])
    float v0 = a0 + teos;
    float v1 = a1 + teos;
    float m0 = v0, m1 = v1;
#pragma unroll
    for (int off = 16; off > 0; off >>= 1){
        m0 = fmaxf(m0, __shfl_xor_sync(0xffffffffu, m0, off));
        m1 = fmaxf(m1, __shfl_xor_sync(0xffffffffu, m1, off));
    }
    float e0 = ex2f((v0 - m0) * LOG2E);
    float e1 = ex2f((v1 - m1) * LOG2E);
#pragma unroll
    for (int off = 16; off > 0; off >>= 1){
        e0 += __shfl_xor_sync(0xffffffffu, e0, off);
        e1 += __shfl_xor_sync(0xffffffffu, e1, off);
    }
    if (lane == 0){
        out[b0] = C0 + m0 + lg2f_(e0) * LN2F;
        if (has_b1) out[b1] = C1 + m1 + lg2f_(e1) * LN2F;
    }
}

extern "C" void kernel_launch(void* const* d_in, const int* in_sizes, int n_in,
                              void* d_out, int out_size)
{
    const float* feats = (const float*)d_in[0];
    const float* mask  = (const float*)d_in[1];
    const float* trans = (const float*)d_in[2];
    float* out = (float*)d_out;

    const int batch = out_size;                 // out is (batch,)
    const int seq   = in_sizes[1] / batch;      // mask is (seq, batch)

    const int npairs = (batch + 1) >> 1;        // 2 batches per warp
    const int warps_per_cta = 4;                // 128 threads
    const int blocks = (npairs + warps_per_cta - 1) / warps_per_cta;

    crf_fwd<<<blocks, warps_per_cta * 32>>>(feats, mask, trans, out, seq, batch);
}

// round 2
// speedup vs baseline: 1.0874x; 1.0874x over previous
#include <cuda_runtime.h>

#define NCLS 32
#define SOSC 30
#define EOSC 31
#define LOG2E 1.4426950408889634f
#define LN2F  0.6931471805599453f

typedef unsigned long long u64;

__device__ __forceinline__ float ex2f(float x){ float r; asm("ex2.approx.f32 %0, %1;" : "=f"(r) : "f"(x)); return r; }
__device__ __forceinline__ float lg2f_(float x){ float r; asm("lg2.approx.f32 %0, %1;" : "=f"(r) : "f"(x)); return r; }
__device__ __forceinline__ float rcpf(float x){ float r; asm("rcp.approx.f32 %0, %1;" : "=f"(r) : "f"(x)); return r; }
__device__ __forceinline__ u64 pk2(float lo, float hi){ u64 r; asm("mov.b64 %0, {%1,%2};" : "=l"(r) : "f"(lo), "f"(hi)); return r; }
__device__ __forceinline__ void up2(u64 v, float& lo, float& hi){ asm("mov.b64 {%0,%1}, %2;" : "=f"(lo), "=f"(hi) : "l"(v)); }
__device__ __forceinline__ u64 ffma2(u64 a, u64 b, u64 c){ u64 d; asm("fma.rn.f32x2 %0, %1, %2, %3;" : "=l"(d) : "l"(a), "l"(b), "l"(c)); return d; }
__device__ __forceinline__ u64 fadd2(u64 a, u64 b){ u64 d; asm("add.rn.f32x2 %0, %1, %2;" : "=l"(d) : "l"(a), "l"(b)); return d; }
__device__ __forceinline__ u64 fmul2(u64 a, u64 b){ u64 d; asm("mul.rn.f32x2 %0, %1, %2;" : "=l"(d) : "l"(a), "l"(b)); return d; }
__device__ __forceinline__ u64 fsub2(u64 a, u64 b){ u64 d; asm("sub.rn.f32x2 %0, %1, %2;" : "=l"(d) : "l"(a), "l"(b)); return d; }

// Exp-domain CRF forward. 1 warp = 2 batches (f32x2), lane = class.
// P_{t+1}[c] = fexp_t[c] * sum_k E[c,k] * P_t[k]; ex2(feat) precomputed in the
// prefetch (off critical path); lg2 only feeds the scalar offset C (side chain);
// shfl-rescale amortized to every 4th step. Mask blend is exp-domain linear
// (exact for m in {0,1}); guarded log-domain slow path for fractional m.
__global__ __launch_bounds__(256)
void crf_fwd(const float* __restrict__ feats,
             const float* __restrict__ mask,
             const float* __restrict__ trans,
             float* __restrict__ out,
             int seq, int batch)
{
    __shared__ __align__(16) u64 pbuf[8][2][NCLS];
    const int lane = threadIdx.x & 31;
    const int wl   = threadIdx.x >> 5;
    const int pair = blockIdx.x * 8 + wl;
    const int npairs = (batch + 1) >> 1;
    if (pair >= npairs) return;
    const int b0 = pair * 2;
    int b1 = b0 + 1;
    const bool has_b1 = (b1 < batch);
    if (!has_b1) b1 = b0;

    // E[c,k] = exp(T[c,k]) duplicated into both halves. NEG row/col -> exact 0.
    u64 E2[NCLS];
#pragma unroll
    for (int k = 0; k < NCLS; ++k){
        float e = ex2f(trans[lane * NCLS + k] * LOG2E);
        E2[k] = pk2(e, e);
    }
    const float ee = ex2f(trans[EOSC * NCLS + lane] * LOG2E);  // exp(T[EOS,lane])

    // State: P = exp(alpha - C), C in log2 units.
    float pinit = (lane == SOSC) ? 1.0f : 0.0f;
    u64 P2 = pk2(pinit, pinit);
    float C0 = 0.0f, C1 = 0.0f;

    const size_t fstride = (size_t)batch * NCLS;
    const float* fpA = feats + (size_t)b0 * NCLS + lane;
    const float* fpB = feats + (size_t)b1 * NCLS + lane;
    const float* mpA = mask + b0;
    const float* mpB = mask + b1;

    // 8-deep prefetch: fexp = exp(feat) computed here, OFF the critical path.
    u64 fexp2[8], m2[8];
#pragma unroll
    for (int j = 0; j < 8; ++j){
        int tc = (j < seq) ? j : (seq - 1);
        float fa = fpA[(size_t)tc * fstride];
        float fb = fpB[(size_t)tc * fstride];
        fexp2[j] = pk2(ex2f(fa * LOG2E), ex2f(fb * LOG2E));
        m2[j] = pk2(mpA[(size_t)tc * batch], mpB[(size_t)tc * batch]);
    }

    int t = 0;
    for (int t0 = 0; t0 + 8 <= seq; t0 += 8){
#pragma unroll
        for (int j = 0; j < 8; ++j){
            const int buf = j & 1;
            pbuf[wl][buf][lane] = P2;           // broadcast P to warp
            __syncwarp();
            const u64* pb = pbuf[wl][buf];
            u64 a0 = 0ull, a1 = 0ull, a2 = 0ull, a3 = 0ull;
            u64 a4 = 0ull, a5 = 0ull, a6 = 0ull, a7 = 0ull;
#pragma unroll
            for (int k = 0; k < NCLS; k += 8){
                ulonglong2 q0 = *reinterpret_cast<const ulonglong2*>(&pb[k]);
                ulonglong2 q1 = *reinterpret_cast<const ulonglong2*>(&pb[k+2]);
                ulonglong2 q2 = *reinterpret_cast<const ulonglong2*>(&pb[k+4]);
                ulonglong2 q3 = *reinterpret_cast<const ulonglong2*>(&pb[k+6]);
                a0 = ffma2(E2[k],   q0.x, a0);
                a1 = ffma2(E2[k+1], q0.y, a1);
                a2 = ffma2(E2[k+2], q1.x, a2);
                a3 = ffma2(E2[k+3], q1.y, a3);
                a4 = ffma2(E2[k+4], q2.x, a4);
                a5 = ffma2(E2[k+5], q2.y, a5);
                a6 = ffma2(E2[k+6], q3.x, a6);
                a7 = ffma2(E2[k+7], q3.y, a7);
            }
            u64 s2 = fadd2(fadd2(fadd2(a0,a1), fadd2(a2,a3)),
                           fadd2(fadd2(a4,a5), fadd2(a6,a7)));
            u64 Pn = fmul2(s2, fexp2[j]);       // * exp(feat)
            // exp-domain linear blend (exact for m in {0,1})
            u64 mm = m2[j];
            u64 Pold = P2;
            P2 = ffma2(mm, fsub2(Pn, P2), P2);
            float mk0, mk1; up2(mm, mk0, mk1);
            if (__builtin_expect(mk0*(1.0f-mk0) != 0.0f || mk1*(1.0f-mk1) != 0.0f, 0)){
                // fractional mask: exact log-domain blend (rare path)
                float po0, po1, pn0, pn1;
                up2(Pold, po0, po1); up2(Pn, pn0, pn1);
                float r0 = ex2f(mk0*lg2f_(pn0) + (1.0f-mk0)*lg2f_(po0));
                float r1 = ex2f(mk1*lg2f_(pn1) + (1.0f-mk1)*lg2f_(po1));
                P2 = pk2(r0, r1);
            }
            if ((j & 3) == 3){                   // rescale every 4 steps
                float p0, p1; up2(P2, p0, p1);
                float d0 = __shfl_sync(0xffffffffu, p0, 0);
                float d1 = __shfl_sync(0xffffffffu, p1, 0);
                float r0 = (d0 > 1e-30f) ? rcpf(d0) : 1.0f;
                float r1 = (d1 > 1e-30f) ? rcpf(d1) : 1.0f;
                P2 = fmul2(P2, pk2(r0, r1));
                C0 -= lg2f_(r0);                 // side chain, never blocks
                C1 -= lg2f_(r1);
            }
            // prefetch step t0+8+j
            int tn = t0 + 8 + j;
            int tc = (tn < seq) ? tn : (seq - 1);
            float fa = fpA[(size_t)tc * fstride];
            float fb = fpB[(size_t)tc * fstride];
            fexp2[j] = pk2(ex2f(fa * LOG2E), ex2f(fb * LOG2E));
            m2[j] = pk2(mpA[(size_t)tc * batch], mpB[(size_t)tc * batch]);
        }
        t = t0 + 8;
    }
    // tail (seq % 8 != 0; not hit for seq=512)
    for (; t < seq; ++t){
        const int buf = t & 1;
        pbuf[wl][buf][lane] = P2;
        __syncwarp();
        const u64* pb = pbuf[wl][buf];
        u64 a0 = 0ull, a1 = 0ull, a2 = 0ull, a3 = 0ull;
#pragma unroll
        for (int k = 0; k < NCLS; k += 4){
            ulonglong2 q0 = *reinterpret_cast<const ulonglong2*>(&pb[k]);
            ulonglong2 q1 = *reinterpret_cast<const ulonglong2*>(&pb[k+2]);
            a0 = ffma2(E2[k],   q0.x, a0);
            a1 = ffma2(E2[k+1], q0.y, a1);
            a2 = ffma2(E2[k+2], q1.x, a2);
            a3 = ffma2(E2[k+3], q1.y, a3);
        }
        u64 s2 = fadd2(fadd2(a0,a1), fadd2(a2,a3));
        float fa = fpA[(size_t)t * fstride];
        float fb = fpB[(size_t)t * fstride];
        u64 Pn = fmul2(s2, pk2(ex2f(fa*LOG2E), ex2f(fb*LOG2E)));
        float mk0 = mpA[(size_t)t * batch];
        float mk1 = mpB[(size_t)t * batch];
        u64 mm = pk2(mk0, mk1);
        u64 Pold = P2;
        P2 = ffma2(mm, fsub2(Pn, P2), P2);
        if (__builtin_expect(mk0*(1.0f-mk0) != 0.0f || mk1*(1.0f-mk1) != 0.0f, 0)){
            float po0, po1, pn0, pn1;
            up2(Pold, po0, po1); up2(Pn, pn0, pn1);
            float r0 = ex2f(mk0*lg2f_(pn0) + (1.0f-mk0)*lg2f_(po0));
            float r1 = ex2f(mk1*lg2f_(pn1) + (1.0f-mk1)*lg2f_(po1));
            P2 = pk2(r0, r1);
        }
        {   // rescale every tail step (cheap, rare)
            float p0, p1; up2(P2, p0, p1);
            float d0 = __shfl_sync(0xffffffffu, p0, 0);
            float d1 = __shfl_sync(0xffffffffu, p1, 0);
            float r0 = (d0 > 1e-30f) ? rcpf(d0) : 1.0f;
            float r1 = (d1 > 1e-30f) ? rcpf(d1) : 1.0f;
            P2 = fmul2(P2, pk2(r0, r1));
            C0 -= lg2f_(r0);
            C1 -= lg2f_(r1);
        }
    }

    // Epilogue: out[b] = ln2 * (C + log2( sum_c P[c] * exp(T[EOS,c]) ))
    float p0, p1; up2(P2, p0, p1);
    float v0 = p0 * ee;
    float v1 = p1 * ee;
#pragma unroll
    for (int off = 16; off > 0; off >>= 1){
        v0 += __shfl_xor_sync(0xffffffffu, v0, off);
        v1 += __shfl_xor_sync(0xffffffffu, v1, off);
    }
    if (lane == 0){
        out[b0] = (C0 + lg2f_(v0)) * LN2F;
        if (has_b1) out[b1] = (C1 + lg2f_(v1)) * LN2F;
    }
}

extern "C" void kernel_launch(void* const* d_in, const int* in_sizes, int n_in,
                              void* d_out, int out_size)
{
    const float* feats = (const float*)d_in[0];
    const float* mask  = (const float*)d_in[1];
    const float* trans = (const float*)d_in[2];
    float* out = (float*)d_out;

    const int batch = out_size;                 // out is (batch,)
    const int seq   = in_sizes[1] / batch;      // mask is (seq, batch)

    const int npairs = (batch + 1) >> 1;        // 2 batches per warp
    const int warps_per_cta = 8;                // 256 threads -> 128 CTAs for batch=2048
    const int blocks = (npairs + warps_per_cta - 1) / warps_per_cta;

    crf_fwd<<<blocks, warps_per_cta * 32>>>(feats, mask, trans, out, seq, batch);
}